// round 13
// baseline (speedup 1.0000x reference)
#include <cuda_runtime.h>
#include <cuda_bf16.h>
#include <math.h>
#include <stdint.h>

#define B_ 256
#define S_ 512
#define V_ 32000
#define E_ 1024
#define H_ 1024
#define O_ 512
#define NCTA 128

// ---------------------------------------------------------------------------
// Device scratch
// Z-quad layout (bf16 hi/lo) per row of K=1024:
//   1024 u32 per row; for k16 block KB, t in 0..3: uint4 at u32 (KB*16 + t*4) =
//   [hiPair(2t,2t+1), hiPair(2t+8,2t+9), loPair(2t,2t+1), loPair(2t+8,2t+9)]
// ---------------------------------------------------------------------------
__device__ float    g_embp[(size_t)V_ * H_];    // projected embedding table (128 MB)
__device__ float    g_hf[B_ * H_];              // final hidden state (fp32 plain)
__device__ uint32_t g_wz[H_ * 1024];            // W_hh  Z-layout (4 MB)
__device__ uint32_t g_wihz[H_ * 1024];          // W_ih  Z-layout (4 MB)
__device__ uint32_t g_embz[(size_t)V_ * 1024];  // emb Z-layout (128 MB)
__device__ uint32_t g_hz[3][B_ * 1024];         // h Z-layout, TRIPLE buffered
__device__ int      g_flag2[NCTA];              // per-CTA completed-step flags

// conflict-free row mask: adjacent rows differ by 4 in the low-3 slot space
#define MROW(r) ((((r) & 1) << 2) | (((r) >> 1) & 3))

// ---------------------------------------------------------------------------
// Helpers
// ---------------------------------------------------------------------------
__device__ __forceinline__ uint32_t smem_u32(const void* p) {
    uint32_t a;
    asm("{ .reg .u64 t; cvta.to.shared.u64 t, %1; cvt.u32.u64 %0, t; }" : "=r"(a) : "l"(p));
    return a;
}
__device__ __forceinline__ uint32_t pack_bf16(float lo, float hi) {
    uint32_t u; asm("cvt.rn.bf16x2.f32 %0, %1, %2;" : "=r"(u) : "f"(hi), "f"(lo));
    return u;
}
__device__ __forceinline__ void wait_ge(const int* f, int s) {
    int v;
    asm volatile("ld.acquire.gpu.global.s32 %0, [%1];" : "=r"(v) : "l"(f) : "memory");
    while (v < s) {
        __nanosleep(20);
        asm volatile("ld.acquire.gpu.global.s32 %0, [%1];" : "=r"(v) : "l"(f) : "memory");
    }
}

#define CP_ASYNC16(dst, src) \
    asm volatile("cp.async.cg.shared.global [%0], [%1], 16;" :: "r"(dst), "l"(src))
#define CP_COMMIT() asm volatile("cp.async.commit_group;" ::: "memory")
#define CP_WAIT0()  asm volatile("cp.async.wait_group 0;" ::: "memory")
#define CP_WAIT1()  asm volatile("cp.async.wait_group 1;" ::: "memory")
#define CP_WAIT2()  asm volatile("cp.async.wait_group 2;" ::: "memory")

// D += A*B  (m16n8k16 bf16, row.col, fp32 accum)
__device__ __forceinline__ void mma_bf16(float* c,
    uint32_t a0, uint32_t a1, uint32_t a2, uint32_t a3, uint32_t b0, uint32_t b1)
{
    asm volatile(
        "mma.sync.aligned.m16n8k16.row.col.f32.bf16.bf16.f32 "
        "{%0,%1,%2,%3}, {%4,%5,%6,%7}, {%8,%9}, {%0,%1,%2,%3};"
        : "+f"(c[0]), "+f"(c[1]), "+f"(c[2]), "+f"(c[3])
        : "r"(a0), "r"(a1), "r"(a2), "r"(a3), "r"(b0), "r"(b1));
}

// ---------------------------------------------------------------------------
// Persistent scan kernel — slab-granular producer/consumer dataflow.
// 128 CTAs x 512 thr (16 warps). CTA tile M=64 x N=32.
// Warp wid = kgrp*2 + mslot. One __syncthreads per K iteration.
// Dependencies: before loading k-slab j at step s, each thread waits for
// flag[mblk*32 + 4j + (cc>>3)] >= s (the CTA that produced its chunk).
// h is triple-buffered so fast CTAs may run ahead without WAR hazards.
// ---------------------------------------------------------------------------
#define W_BYTES   131072
#define STG_BYTES 32768
#define SCAN_SMEM (W_BYTES + 3 * STG_BYTES)   // 229376
#define NIT 8

__global__ __launch_bounds__(512, 1) void rnn_scan_kernel(
    const int* __restrict__ x, const float* __restrict__ b_hh)
{
    extern __shared__ char sm[];
    char* smW = sm;
    char* smA = sm + W_BYTES;
    const uint32_t smWu = smem_u32(smW);
    const uint32_t smAu = smem_u32(smA);

    const int tid = threadIdx.x;
    const int wid = tid >> 5, lane = tid & 31;
    const int g = lane >> 2, t = lane & 3;
    const int mslot = wid & 1, kgrp = wid >> 1;

    const int cta = blockIdx.x;
    const int nblk = cta & 31, mblk = cta >> 5;
    const int nbase = nblk * 32, mbase = mblk * 64;

    // producer-flag pointer for this thread's load chunk (cc = tid&31)
    const int* flagBase = g_flag2 + mblk * 32 + ((tid & 31) >> 3);

    // ---- resident W slice load (once): 32 rows x 256 chunks ----
    for (int j = 0; j < 16; j++) {
        int idx = tid + j * 512;
        int n = idx >> 8, c = idx & 255;
        int mr = MROW(n);
        uint32_t dst = smWu + n * 4096 + (((c & ~7) | ((c ^ mr) & 7)) << 4);
        CP_ASYNC16(dst, g_wz + (((size_t)(nbase + n)) << 10) + (c << 2));
    }
    CP_COMMIT(); CP_WAIT0();
    __syncthreads();

    // ---- thread-constant MMA operand offsets ----
    const int gm = MROW(g);
    const int achunk = ((kgrp & 6) << 2) + (((((kgrp & 1) << 2) + t)) ^ gm);
    const uint32_t abase = (uint32_t)achunk << 4;
    uint32_t aoff[4];
#pragma unroll
    for (int mt = 0; mt < 2; mt++)
#pragma unroll
        for (int hf = 0; hf < 2; hf++)
            aoff[mt * 2 + hf] = (mslot * 32 + mt * 16 + hf * 8 + g) * 512 + abase;
    uint32_t woff[4];
#pragma unroll
    for (int nt = 0; nt < 4; nt++)
        woff[nt] = (nt * 8 + g) * 4096 + abase;

    // ---- epilogue thread-constant mapping ----
    const int erow = tid >> 3;
    const int pc = tid & 7;
    const int mslot_r = erow >> 5, mt_r = (erow >> 4) & 1;
    const int hf_r = (erow >> 3) & 1, g_r = erow & 7;
    const size_t growbase = ((size_t)(mbase + erow)) << 10;
    const int* xrow = x + (mbase + erow) * S_;     // tokens for this output row

    int roff[2], colv[2], zoff[2];
    float2 bvv[2];
#pragma unroll
    for (int i = 0; i < 2; i++) {
        int p = pc + i * 8;
        int nt_r = p >> 2, t_r = p & 3;
        int lane_r = g_r * 4 + t_r;
        int q_r = mt_r * 4 + nt_r;
        roff[i] = lane_r * 32 + ((q_r ^ (lane_r & 7)) << 2) + 2 * hf_r;
        int col = nbase + 2 * p;
        colv[i] = col;
        bvv[i] = *(const float2*)(b_hh + col);
        int kb = col >> 4;
        int pp = (col >> 1) & 7;
        zoff[i] = kb * 16 + (pp & 3) * 4 + (pp >> 2);
    }

    float* dumpf = (float*)smA;

#pragma unroll 1
    for (int s = 0; s < S_; s++) {
        const uint32_t* hzin = g_hz[s % 3];
        uint32_t* hzout = g_hz[(s + 1) % 3];

        // ---- prefetch epilogue xp = emb_proj[token] (hidden under MMA) ----
        const int tok = xrow[s];
        const float* eprow = g_embp + ((size_t)tok << 10);
        float2 xvv[2];
#pragma unroll
        for (int i = 0; i < 2; i++)
            xvv[i] = *(const float2*)(eprow + colv[i]);

        // ---- prefill stages 0,1 (k-slabs 0,1) with producer waits ----
#pragma unroll
        for (int st = 0; st < 2; st++) {
            wait_ge(flagBase + st * 4, s);
#pragma unroll
            for (int j = 0; j < 4; j++) {
                int idx = tid + j * 512;
                int row = idx >> 5, cc = idx & 31;
                int mr = MROW(row);
                uint32_t dst = smAu + st * STG_BYTES + row * 512 +
                               (((cc & ~7) | ((cc ^ mr) & 7)) << 4);
                CP_ASYNC16(dst, hzin + (((size_t)(mbase + row)) << 10) +
                                ((st * 32 + cc) << 2));
            }
            CP_COMMIT();
        }

        float acc[8][4];
#pragma unroll
        for (int q = 0; q < 8; q++)
#pragma unroll
            for (int i = 0; i < 4; i++) acc[q][i] = 0.f;

        // ---- K loop: one sync per iteration ----
#pragma unroll
        for (int it = 0; it < NIT; it++) {
            if (it < NIT - 1) { CP_WAIT1(); } else { CP_WAIT0(); }
            __syncthreads();

            if (it + 2 < NIT) {
                int st = (it + 2) % 3;
                wait_ge(flagBase + (it + 2) * 4, s);
#pragma unroll
                for (int j = 0; j < 4; j++) {
                    int idx = tid + j * 512;
                    int row = idx >> 5, cc = idx & 31;
                    int mr = MROW(row);
                    uint32_t dst = smAu + st * STG_BYTES + row * 512 +
                                   (((cc & ~7) | ((cc ^ mr) & 7)) << 4);
                    CP_ASYNC16(dst, hzin + (((size_t)(mbase + row)) << 10) +
                                    (((it + 2) * 32 + cc) << 2));
                }
                CP_COMMIT();
            }

            const char* stg = smA + (it % 3) * STG_BYTES;
            uint4 aq[2][2];
#pragma unroll
            for (int mt = 0; mt < 2; mt++)
#pragma unroll
                for (int hf = 0; hf < 2; hf++)
                    aq[mt][hf] = *(const uint4*)(stg + aoff[mt * 2 + hf]);
            uint4 wq[4];
#pragma unroll
            for (int nt = 0; nt < 4; nt++)
                wq[nt] = *(const uint4*)(smW + woff[nt] + it * 512);

#pragma unroll
            for (int nt = 0; nt < 4; nt++)
#pragma unroll
                for (int mt = 0; mt < 2; mt++)
                    mma_bf16(acc[mt * 4 + nt], aq[mt][0].x, aq[mt][1].x,
                             aq[mt][0].y, aq[mt][1].y, wq[nt].x, wq[nt].y);
#pragma unroll
            for (int nt = 0; nt < 4; nt++)
#pragma unroll
                for (int mt = 0; mt < 2; mt++)
                    mma_bf16(acc[mt * 4 + nt], aq[mt][0].x, aq[mt][1].x,
                             aq[mt][0].y, aq[mt][1].y, wq[nt].z, wq[nt].w);
#pragma unroll
            for (int nt = 0; nt < 4; nt++)
#pragma unroll
                for (int mt = 0; mt < 2; mt++)
                    mma_bf16(acc[mt * 4 + nt], aq[mt][0].z, aq[mt][1].z,
                             aq[mt][0].w, aq[mt][1].w, wq[nt].x, wq[nt].y);
        }

        __syncthreads();   // stage smem free -> reuse as reduction buffer

        // ---- dump partials: 16 warps x 4 KB = 64 KB ----
        {
            float* wr = dumpf + wid * 1024 + lane * 32;
#pragma unroll
            for (int q = 0; q < 8; q++)
                *(float4*)(wr + ((q ^ (lane & 7)) << 2)) =
                    make_float4(acc[q][0], acc[q][1], acc[q][2], acc[q][3]);
        }
        __syncthreads();

        // ---- epilogue: 8-way K reduce + tanh + Z-pack store ----
#pragma unroll
        for (int i = 0; i < 2; i++) {
            float s0 = 0.f, s1 = 0.f;
#pragma unroll
            for (int k = 0; k < 8; k++) {
                const float* rr = dumpf + (k * 2 + mslot_r) * 1024 + roff[i];
                s0 += rr[0]; s1 += rr[1];
            }
            float v0 = tanhf(s0 + xvv[i].x + bvv[i].x);
            float v1 = tanhf(s1 + xvv[i].y + bvv[i].y);

            uint32_t hiU = pack_bf16(v0, v1);
            float r0 = v0 - __uint_as_float(hiU << 16);
            float r1 = v1 - __uint_as_float(hiU & 0xFFFF0000u);
            uint32_t loU = pack_bf16(r0, r1);

            uint32_t* dst = hzout + growbase + zoff[i];
            dst[0] = hiU;
            dst[2] = loU;

            if (s == S_ - 1)
                *(float2*)(g_hf + growbase + colv[i]) = make_float2(v0, v1);
        }

        // ---- publish: fence all writes, then release flag = s+1 ----
        __threadfence();
        __syncthreads();   // also protects dumpf from next-step prefill
        if (tid == 0)
            asm volatile("st.release.gpu.global.s32 [%0], %1;"
                         :: "l"(g_flag2 + cta), "r"(s + 1) : "memory");
    }
}

// ---------------------------------------------------------------------------
// Dense embedding-table projection: emb_proj = emb @ W_ih^T + b_ih
// M over V=32000 rows (250 tiles of 128), N=1024 (8 tiles of 128).
// ---------------------------------------------------------------------------
#define PJ_STG 65536
#define PJ_SMEM (3 * PJ_STG)
#define PJ_NIT 16

__global__ __launch_bounds__(256, 1) void embtab_mma_kernel(const float* __restrict__ b_ih)
{
    extern __shared__ char sm[];
    const uint32_t smu = smem_u32(sm);

    const int tid = threadIdx.x;
    const int wid = tid >> 5, lane = tid & 31;
    const int g = lane >> 2, t = lane & 3;
    const int mslot = wid & 1, nslot = wid >> 1;

    const int nbase = blockIdx.x * 128;
    const int mbase = blockIdx.y * 128;

    const int lrow = tid >> 4;
    const int lcc  = tid & 15;
    const uint32_t lpos = (uint32_t)((lcc ^ (lrow & 7)) << 4);
    const uint32_t* asrc = g_embz + (size_t)(mbase + lrow) * 1024 + lcc * 4;
    const uint32_t* bsrc = g_wihz + (size_t)(nbase + lrow) * 1024 + lcc * 4;

    float acc[4][4][4];
#pragma unroll
    for (int mt = 0; mt < 4; mt++)
#pragma unroll
        for (int nt = 0; nt < 4; nt++)
#pragma unroll
            for (int i = 0; i < 4; i++) acc[mt][nt][i] = 0.f;

#pragma unroll
    for (int st = 0; st < 2; st++) {
        uint32_t sb = smu + st * PJ_STG;
        int k0 = st * 64;
#pragma unroll
        for (int j = 0; j < 8; j++) {
            uint32_t d = (lrow + 16 * j) * 256 + lpos;
            CP_ASYNC16(sb + d, asrc + (size_t)j * 16 * 1024 + k0);
            CP_ASYNC16(sb + 32768 + d, bsrc + (size_t)j * 16 * 1024 + k0);
        }
        CP_COMMIT();
    }

    const char* Ab = sm + (mslot * 64 + g) * 256;
    const char* Bb = sm + 32768 + (nslot * 32 + g) * 256;

    for (int it = 0; it < PJ_NIT; it++) {
        if (it + 2 < PJ_NIT) {
            uint32_t sb = smu + ((it + 2) % 3) * PJ_STG;
            int k0 = (it + 2) * 64;
#pragma unroll
            for (int j = 0; j < 8; j++) {
                uint32_t d = (lrow + 16 * j) * 256 + lpos;
                CP_ASYNC16(sb + d, asrc + (size_t)j * 16 * 1024 + k0);
                CP_ASYNC16(sb + 32768 + d, bsrc + (size_t)j * 16 * 1024 + k0);
            }
            CP_COMMIT();
            CP_WAIT2();
        } else if (it + 1 < PJ_NIT) {
            CP_WAIT1();
        } else {
            CP_WAIT0();
        }
        __syncthreads();

        const int stOff = (it % 3) * PJ_STG;
#pragma unroll
        for (int kb = 0; kb < 4; kb++) {
            const int pos = ((kb * 4 + t) ^ g) << 4;
            uint4 aq[4][2];
#pragma unroll
            for (int mt = 0; mt < 4; mt++)
#pragma unroll
                for (int hf = 0; hf < 2; hf++)
                    aq[mt][hf] = *(const uint4*)(Ab + stOff +
                                 (mt * 16 + hf * 8) * 256 + pos);
            uint4 wq[4];
#pragma unroll
            for (int nt = 0; nt < 4; nt++)
                wq[nt] = *(const uint4*)(Bb + stOff + nt * 8 * 256 + pos);

#pragma unroll
            for (int nt = 0; nt < 4; nt++)
#pragma unroll
                for (int mt = 0; mt < 4; mt++)
                    mma_bf16(acc[mt][nt], aq[mt][0].x, aq[mt][1].x,
                             aq[mt][0].y, aq[mt][1].y, wq[nt].x, wq[nt].y);
#pragma unroll
            for (int nt = 0; nt < 4; nt++)
#pragma unroll
                for (int mt = 0; mt < 4; mt++)
                    mma_bf16(acc[mt][nt], aq[mt][0].x, aq[mt][1].x,
                             aq[mt][0].y, aq[mt][1].y, wq[nt].z, wq[nt].w);
#pragma unroll
            for (int nt = 0; nt < 4; nt++)
#pragma unroll
                for (int mt = 0; mt < 4; mt++)
                    mma_bf16(acc[mt][nt], aq[mt][0].z, aq[mt][1].z,
                             aq[mt][0].w, aq[mt][1].w, wq[nt].x, wq[nt].y);
        }
        __syncthreads();
    }

    float2 bv[4];
#pragma unroll
    for (int nt = 0; nt < 4; nt++)
        bv[nt] = *(const float2*)(b_ih + nbase + nslot * 32 + nt * 8 + 2 * t);

#pragma unroll
    for (int mt = 0; mt < 4; mt++) {
        const size_t r0 = (size_t)(mbase + mslot * 64 + mt * 16 + g) * H_;
        const size_t r1 = r0 + 8 * H_;
#pragma unroll
        for (int nt = 0; nt < 4; nt++) {
            const int col = nbase + nslot * 32 + nt * 8 + 2 * t;
            *(float2*)(g_embp + r0 + col) =
                make_float2(acc[mt][nt][0] + bv[nt].x, acc[mt][nt][1] + bv[nt].y);
            *(float2*)(g_embp + r1 + col) =
                make_float2(acc[mt][nt][2] + bv[nt].x, acc[mt][nt][3] + bv[nt].y);
        }
    }
}

// ---------------------------------------------------------------------------
// Classifier GEMM (scalar, tiny)
// ---------------------------------------------------------------------------
__global__ __launch_bounds__(256) void gemm_clf(
    const float* __restrict__ A, const float* __restrict__ W,
    const float* __restrict__ bias, float* __restrict__ C, int N, int K)
{
    __shared__ float As[16][36];
    __shared__ float Bs[16][68];

    const int tid = threadIdx.x;
    const int rowBase = blockIdx.y * 32;
    const int colBase = blockIdx.x * 64;
    const int tr = tid >> 5;
    const int tc = tid & 31;

    float acc[4][2];
#pragma unroll
    for (int i = 0; i < 4; i++) { acc[i][0] = 0.f; acc[i][1] = 0.f; }

    for (int k0 = 0; k0 < K; k0 += 16) {
        if (tid < 128) {
            int m = tid >> 2, q = tid & 3;
            float4 a = *(const float4*)(A + (size_t)(rowBase + m) * K + k0 + q * 4);
            As[q * 4 + 0][m] = a.x; As[q * 4 + 1][m] = a.y;
            As[q * 4 + 2][m] = a.z; As[q * 4 + 3][m] = a.w;
        }
        {
            int n = tid >> 2, q = tid & 3;
            float4 w = *(const float4*)(W + (size_t)(colBase + n) * K + k0 + q * 4);
            Bs[q * 4 + 0][n] = w.x; Bs[q * 4 + 1][n] = w.y;
            Bs[q * 4 + 2][n] = w.z; Bs[q * 4 + 3][n] = w.w;
        }
        __syncthreads();

#pragma unroll
        for (int kk = 0; kk < 16; kk++) {
            float ra[4], rb[2];
#pragma unroll
            for (int i = 0; i < 4; i++) ra[i] = As[kk][tr * 4 + i];
            rb[0] = Bs[kk][tc * 2 + 0];
            rb[1] = Bs[kk][tc * 2 + 1];
#pragma unroll
            for (int i = 0; i < 4; i++) {
                acc[i][0] += ra[i] * rb[0];
                acc[i][1] += ra[i] * rb[1];
            }
        }
        __syncthreads();
    }

#pragma unroll
    for (int i = 0; i < 4; i++) {
        int row = rowBase + tr * 4 + i;
#pragma unroll
        for (int j = 0; j < 2; j++) {
            int col = colBase + tc * 2 + j;
            C[(size_t)row * N + col] = acc[i][j] + bias[col];
        }
    }
}

// ---------------------------------------------------------------------------
// Init kernels
// ---------------------------------------------------------------------------
__global__ void zero_init_kernel() {
    int i = blockIdx.x * blockDim.x + threadIdx.x;
    if (i < B_ * 1024) g_hz[0][i] = 0u;
    if (i < NCTA) g_flag2[i] = 0;
}

// fp32 [rows, 1024] -> Z-layout bf16 hi/lo
__global__ void split_kernel(const float* __restrict__ W, uint32_t* __restrict__ dst,
                             int rows)
{
    int idx = blockIdx.x * blockDim.x + threadIdx.x;
    if (idx >= rows * 512) return;
    int n = idx >> 9, p = idx & 511;
    int col = 2 * p;
    float w0 = W[(size_t)n * 1024 + col];
    float w1 = W[(size_t)n * 1024 + col + 1];
    uint32_t hiU = pack_bf16(w0, w1);
    float r0 = w0 - __uint_as_float(hiU << 16);
    float r1 = w1 - __uint_as_float(hiU & 0xFFFF0000u);
    uint32_t loU = pack_bf16(r0, r1);
    int kb = col >> 4;
    int pp = (col >> 1) & 7;
    uint32_t* d = dst + ((size_t)n << 10) + kb * 16 + (pp & 3) * 4;
    d[pp >> 2] = hiU;
    d[(pp >> 2) + 2] = loU;
}

// ---------------------------------------------------------------------------
extern "C" void kernel_launch(void* const* d_in, const int* in_sizes, int n_in,
                              void* d_out, int out_size)
{
    const int*   x     = (const int*)d_in[0];
    const float* emb   = (const float*)d_in[1];
    const float* W_ih  = (const float*)d_in[2];
    const float* b_ih  = (const float*)d_in[3];
    const float* W_hh  = (const float*)d_in[4];
    const float* b_hh  = (const float*)d_in[5];
    const float* W_clf = (const float*)d_in[6];
    const float* b_clf = (const float*)d_in[7];
    float*       out   = (float*)d_out;

    float* hf = nullptr;
    uint32_t *wz = nullptr, *wihz = nullptr, *embz = nullptr;
    cudaGetSymbolAddress((void**)&hf, g_hf);
    cudaGetSymbolAddress((void**)&wz, g_wz);
    cudaGetSymbolAddress((void**)&wihz, g_wihz);
    cudaGetSymbolAddress((void**)&embz, g_embz);

    static bool attrSet = false;
    if (!attrSet) {
        cudaFuncSetAttribute(rnn_scan_kernel,
                             cudaFuncAttributeMaxDynamicSharedMemorySize, SCAN_SMEM);
        cudaFuncSetAttribute(embtab_mma_kernel,
                             cudaFuncAttributeMaxDynamicSharedMemorySize, PJ_SMEM);
        attrSet = true;
    }

    // init + conversions
    zero_init_kernel<<<(B_ * 1024 + 255) / 256, 256>>>();
    split_kernel<<<(H_ * 512 + 255) / 256, 256>>>(W_hh, wz, H_);
    split_kernel<<<(H_ * 512 + 255) / 256, 256>>>(W_ih, wihz, H_);
    split_kernel<<<(V_ * 512 + 255) / 256, 256>>>(emb, embz, V_);

    // dense table projection: emb_proj = emb @ W_ih^T + b_ih  (V x H)
    embtab_mma_kernel<<<dim3(H_ / 128, V_ / 128), 256, PJ_SMEM>>>(b_ih);

    // full scan in one persistent dataflow kernel (512 threads/CTA)
    rnn_scan_kernel<<<NCTA, 512, SCAN_SMEM>>>(x, b_hh);

    // classifier
    gemm_clf<<<dim3(O_ / 64, B_ / 32), 256>>>(hf, W_clf, b_clf, out, O_, H_);
}

// round 14
// speedup vs baseline: 2.2886x; 2.2886x over previous
#include <cuda_runtime.h>
#include <cuda_bf16.h>
#include <math.h>
#include <stdint.h>

#define B_ 256
#define S_ 512
#define V_ 32000
#define E_ 1024
#define H_ 1024
#define O_ 512
#define NCTA 128

// ---------------------------------------------------------------------------
// Device scratch
// Z-quad layout (bf16 hi/lo) per row of K=1024:
//   1024 u32 per row; for k16 block KB, t in 0..3: uint4 at u32 (KB*16 + t*4) =
//   [hiPair(2t,2t+1), hiPair(2t+8,2t+9), loPair(2t,2t+1), loPair(2t+8,2t+9)]
// ---------------------------------------------------------------------------
__device__ float    g_embp[(size_t)V_ * H_];    // projected embedding table (128 MB)
__device__ float    g_hf[B_ * H_];              // final hidden state (fp32 plain)
__device__ uint32_t g_wz[H_ * 1024];            // W_hh  Z-layout (4 MB)
__device__ uint32_t g_wihz[H_ * 1024];          // W_ih  Z-layout (4 MB)
__device__ uint32_t g_embz[(size_t)V_ * 1024];  // emb Z-layout (128 MB)
__device__ uint32_t g_hz[2][B_ * 1024];         // h Z-layout, double buffered
__device__ int      g_bar;                      // grid barrier counter

// conflict-free row mask: adjacent rows differ by 4 in the low-3 slot space
#define MROW(r) ((((r) & 1) << 2) | (((r) >> 1) & 3))

// ---------------------------------------------------------------------------
// Helpers
// ---------------------------------------------------------------------------
__device__ __forceinline__ uint32_t smem_u32(const void* p) {
    uint32_t a;
    asm("{ .reg .u64 t; cvta.to.shared.u64 t, %1; cvt.u32.u64 %0, t; }" : "=r"(a) : "l"(p));
    return a;
}
__device__ __forceinline__ uint32_t pack_bf16(float lo, float hi) {
    uint32_t u; asm("cvt.rn.bf16x2.f32 %0, %1, %2;" : "=r"(u) : "f"(hi), "f"(lo));
    return u;
}

#define CP_ASYNC16(dst, src) \
    asm volatile("cp.async.cg.shared.global [%0], [%1], 16;" :: "r"(dst), "l"(src))
#define CP_COMMIT() asm volatile("cp.async.commit_group;" ::: "memory")
#define CP_WAIT0()  asm volatile("cp.async.wait_group 0;" ::: "memory")
#define CP_WAIT1()  asm volatile("cp.async.wait_group 1;" ::: "memory")
#define CP_WAIT2()  asm volatile("cp.async.wait_group 2;" ::: "memory")

// D += A*B  (m16n8k16 bf16, row.col, fp32 accum)
__device__ __forceinline__ void mma_bf16(float* c,
    uint32_t a0, uint32_t a1, uint32_t a2, uint32_t a3, uint32_t b0, uint32_t b1)
{
    asm volatile(
        "mma.sync.aligned.m16n8k16.row.col.f32.bf16.bf16.f32 "
        "{%0,%1,%2,%3}, {%4,%5,%6,%7}, {%8,%9}, {%0,%1,%2,%3};"
        : "+f"(c[0]), "+f"(c[1]), "+f"(c[2]), "+f"(c[3])
        : "r"(a0), "r"(a1), "r"(a2), "r"(a3), "r"(b0), "r"(b1));
}

// ---------------------------------------------------------------------------
// Persistent scan kernel (R12 winner structure; xp read directly from the
// projected embedding table — no gather kernel, no g_xp buffer).
// 128 CTAs x 512 thr (16 warps). CTA tile M=64 x N=32.
// Warp wid = kgrp*2 + mslot. One __syncthreads per K iteration.
// ---------------------------------------------------------------------------
#define W_BYTES   131072
#define STG_BYTES 32768
#define SCAN_SMEM (W_BYTES + 3 * STG_BYTES)   // 229376
#define NIT 8

__global__ __launch_bounds__(512, 1) void rnn_scan_kernel(
    const int* __restrict__ x, const float* __restrict__ b_hh)
{
    extern __shared__ char sm[];
    char* smW = sm;
    char* smA = sm + W_BYTES;
    const uint32_t smWu = smem_u32(smW);
    const uint32_t smAu = smem_u32(smA);

    const int tid = threadIdx.x;
    const int wid = tid >> 5, lane = tid & 31;
    const int g = lane >> 2, t = lane & 3;
    const int mslot = wid & 1, kgrp = wid >> 1;

    const int cta = blockIdx.x;
    const int nblk = cta & 31, mblk = cta >> 5;
    const int nbase = nblk * 32, mbase = mblk * 64;

    // ---- resident W slice load (once): 32 rows x 256 chunks ----
    for (int j = 0; j < 16; j++) {
        int idx = tid + j * 512;
        int n = idx >> 8, c = idx & 255;
        int mr = MROW(n);
        uint32_t dst = smWu + n * 4096 + (((c & ~7) | ((c ^ mr) & 7)) << 4);
        CP_ASYNC16(dst, g_wz + (((size_t)(nbase + n)) << 10) + (c << 2));
    }
    CP_COMMIT(); CP_WAIT0();
    __syncthreads();

    // ---- thread-constant MMA operand offsets ----
    const int gm = MROW(g);
    const int achunk = ((kgrp & 6) << 2) + (((((kgrp & 1) << 2) + t)) ^ gm);
    const uint32_t abase = (uint32_t)achunk << 4;
    uint32_t aoff[4];
#pragma unroll
    for (int mt = 0; mt < 2; mt++)
#pragma unroll
        for (int hf = 0; hf < 2; hf++)
            aoff[mt * 2 + hf] = (mslot * 32 + mt * 16 + hf * 8 + g) * 512 + abase;
    uint32_t woff[4];
#pragma unroll
    for (int nt = 0; nt < 4; nt++)
        woff[nt] = (nt * 8 + g) * 4096 + abase;

    // ---- epilogue thread-constant mapping ----
    const int erow = tid >> 3;
    const int pc = tid & 7;
    const int mslot_r = erow >> 5, mt_r = (erow >> 4) & 1;
    const int hf_r = (erow >> 3) & 1, g_r = erow & 7;
    const size_t growbase = ((size_t)(mbase + erow)) << 10;
    const int* xrow = x + (mbase + erow) * S_;   // tokens for this output row

    int roff[2], colv[2], zoff[2];
    float2 bvv[2];
#pragma unroll
    for (int i = 0; i < 2; i++) {
        int p = pc + i * 8;
        int nt_r = p >> 2, t_r = p & 3;
        int lane_r = g_r * 4 + t_r;
        int q_r = mt_r * 4 + nt_r;
        roff[i] = lane_r * 32 + ((q_r ^ (lane_r & 7)) << 2) + 2 * hf_r;
        int col = nbase + 2 * p;
        colv[i] = col;
        bvv[i] = *(const float2*)(b_hh + col);
        int kb = col >> 4;
        int pp = (col >> 1) & 7;
        zoff[i] = kb * 16 + (pp & 3) * 4 + (pp >> 2);
    }

    float* dumpf = (float*)smA;

#pragma unroll 1
    for (int s = 0; s < S_; s++) {
        const uint32_t* hzin = g_hz[s & 1];
        uint32_t* hzout = g_hz[(s + 1) & 1];

        // ---- prefetch xp = emb_proj[token] (token LDG + 2 dependent LDGs,
        //      latency hidden under the 8-iteration MMA loop) ----
        const int tok = xrow[s];
        const float* eprow = g_embp + ((size_t)tok << 10);
        float2 xvv[2];
#pragma unroll
        for (int i = 0; i < 2; i++)
            xvv[i] = *(const float2*)(eprow + colv[i]);

        // ---- prefill stages 0,1 (k-slabs 0,1) ----
#pragma unroll
        for (int st = 0; st < 2; st++) {
#pragma unroll
            for (int j = 0; j < 4; j++) {
                int idx = tid + j * 512;
                int row = idx >> 5, cc = idx & 31;
                int mr = MROW(row);
                uint32_t dst = smAu + st * STG_BYTES + row * 512 +
                               (((cc & ~7) | ((cc ^ mr) & 7)) << 4);
                CP_ASYNC16(dst, hzin + (((size_t)(mbase + row)) << 10) +
                                ((st * 32 + cc) << 2));
            }
            CP_COMMIT();
        }

        float acc[8][4];
#pragma unroll
        for (int q = 0; q < 8; q++)
#pragma unroll
            for (int i = 0; i < 4; i++) acc[q][i] = 0.f;

        // ---- K loop: one sync per iteration ----
#pragma unroll
        for (int it = 0; it < NIT; it++) {
            if (it < NIT - 1) { CP_WAIT1(); } else { CP_WAIT0(); }
            __syncthreads();

            if (it + 2 < NIT) {
                int st = (it + 2) % 3;
#pragma unroll
                for (int j = 0; j < 4; j++) {
                    int idx = tid + j * 512;
                    int row = idx >> 5, cc = idx & 31;
                    int mr = MROW(row);
                    uint32_t dst = smAu + st * STG_BYTES + row * 512 +
                                   (((cc & ~7) | ((cc ^ mr) & 7)) << 4);
                    CP_ASYNC16(dst, hzin + (((size_t)(mbase + row)) << 10) +
                                    (((it + 2) * 32 + cc) << 2));
                }
                CP_COMMIT();
            }

            const char* stg = smA + (it % 3) * STG_BYTES;
            uint4 aq[2][2];
#pragma unroll
            for (int mt = 0; mt < 2; mt++)
#pragma unroll
                for (int hf = 0; hf < 2; hf++)
                    aq[mt][hf] = *(const uint4*)(stg + aoff[mt * 2 + hf]);
            uint4 wq[4];
#pragma unroll
            for (int nt = 0; nt < 4; nt++)
                wq[nt] = *(const uint4*)(smW + woff[nt] + it * 512);

#pragma unroll
            for (int nt = 0; nt < 4; nt++)
#pragma unroll
                for (int mt = 0; mt < 2; mt++)
                    mma_bf16(acc[mt * 4 + nt], aq[mt][0].x, aq[mt][1].x,
                             aq[mt][0].y, aq[mt][1].y, wq[nt].x, wq[nt].y);
#pragma unroll
            for (int nt = 0; nt < 4; nt++)
#pragma unroll
                for (int mt = 0; mt < 2; mt++)
                    mma_bf16(acc[mt * 4 + nt], aq[mt][0].x, aq[mt][1].x,
                             aq[mt][0].y, aq[mt][1].y, wq[nt].z, wq[nt].w);
#pragma unroll
            for (int nt = 0; nt < 4; nt++)
#pragma unroll
                for (int mt = 0; mt < 2; mt++)
                    mma_bf16(acc[mt * 4 + nt], aq[mt][0].z, aq[mt][1].z,
                             aq[mt][0].w, aq[mt][1].w, wq[nt].x, wq[nt].y);
        }

        __syncthreads();   // stage smem free -> reuse as reduction buffer

        // ---- dump partials: 16 warps x 4 KB = 64 KB ----
        {
            float* wr = dumpf + wid * 1024 + lane * 32;
#pragma unroll
            for (int q = 0; q < 8; q++)
                *(float4*)(wr + ((q ^ (lane & 7)) << 2)) =
                    make_float4(acc[q][0], acc[q][1], acc[q][2], acc[q][3]);
        }
        __syncthreads();

        // ---- epilogue: 8-way K reduce + tanh + Z-pack store ----
#pragma unroll
        for (int i = 0; i < 2; i++) {
            float s0 = 0.f, s1 = 0.f;
#pragma unroll
            for (int k = 0; k < 8; k++) {
                const float* rr = dumpf + (k * 2 + mslot_r) * 1024 + roff[i];
                s0 += rr[0]; s1 += rr[1];
            }
            float v0 = tanhf(s0 + xvv[i].x + bvv[i].x);
            float v1 = tanhf(s1 + xvv[i].y + bvv[i].y);

            uint32_t hiU = pack_bf16(v0, v1);
            float r0 = v0 - __uint_as_float(hiU << 16);
            float r1 = v1 - __uint_as_float(hiU & 0xFFFF0000u);
            uint32_t loU = pack_bf16(r0, r1);

            uint32_t* dst = hzout + growbase + zoff[i];
            dst[0] = hiU;
            dst[2] = loU;

            if (s == S_ - 1)
                *(float2*)(g_hf + growbase + colv[i]) = make_float2(v0, v1);
        }

        __syncthreads();

        // ---- grid barrier ----
        if (tid == 0) {
            __threadfence();
            atomicAdd(&g_bar, 1);
            int target = NCTA * (s + 1);
            while (*(volatile int*)&g_bar < target) {}
            __threadfence();
        }
        __syncthreads();
    }
}

// ---------------------------------------------------------------------------
// Dense embedding-table projection: emb_proj = emb @ W_ih^T + b_ih
// M over V=32000 rows (250 tiles of 128), N=1024 (8 tiles of 128).
// ---------------------------------------------------------------------------
#define PJ_STG 65536
#define PJ_SMEM (3 * PJ_STG)
#define PJ_NIT 16

__global__ __launch_bounds__(256, 1) void embtab_mma_kernel(const float* __restrict__ b_ih)
{
    extern __shared__ char sm[];
    const uint32_t smu = smem_u32(sm);

    const int tid = threadIdx.x;
    const int wid = tid >> 5, lane = tid & 31;
    const int g = lane >> 2, t = lane & 3;
    const int mslot = wid & 1, nslot = wid >> 1;

    const int nbase = blockIdx.x * 128;
    const int mbase = blockIdx.y * 128;

    const int lrow = tid >> 4;
    const int lcc  = tid & 15;
    const uint32_t lpos = (uint32_t)((lcc ^ (lrow & 7)) << 4);
    const uint32_t* asrc = g_embz + (size_t)(mbase + lrow) * 1024 + lcc * 4;
    const uint32_t* bsrc = g_wihz + (size_t)(nbase + lrow) * 1024 + lcc * 4;

    float acc[4][4][4];
#pragma unroll
    for (int mt = 0; mt < 4; mt++)
#pragma unroll
        for (int nt = 0; nt < 4; nt++)
#pragma unroll
            for (int i = 0; i < 4; i++) acc[mt][nt][i] = 0.f;

#pragma unroll
    for (int st = 0; st < 2; st++) {
        uint32_t sb = smu + st * PJ_STG;
        int k0 = st * 64;
#pragma unroll
        for (int j = 0; j < 8; j++) {
            uint32_t d = (lrow + 16 * j) * 256 + lpos;
            CP_ASYNC16(sb + d, asrc + (size_t)j * 16 * 1024 + k0);
            CP_ASYNC16(sb + 32768 + d, bsrc + (size_t)j * 16 * 1024 + k0);
        }
        CP_COMMIT();
    }

    const char* Ab = sm + (mslot * 64 + g) * 256;
    const char* Bb = sm + 32768 + (nslot * 32 + g) * 256;

    for (int it = 0; it < PJ_NIT; it++) {
        if (it + 2 < PJ_NIT) {
            uint32_t sb = smu + ((it + 2) % 3) * PJ_STG;
            int k0 = (it + 2) * 64;
#pragma unroll
            for (int j = 0; j < 8; j++) {
                uint32_t d = (lrow + 16 * j) * 256 + lpos;
                CP_ASYNC16(sb + d, asrc + (size_t)j * 16 * 1024 + k0);
                CP_ASYNC16(sb + 32768 + d, bsrc + (size_t)j * 16 * 1024 + k0);
            }
            CP_COMMIT();
            CP_WAIT2();
        } else if (it + 1 < PJ_NIT) {
            CP_WAIT1();
        } else {
            CP_WAIT0();
        }
        __syncthreads();

        const int stOff = (it % 3) * PJ_STG;
#pragma unroll
        for (int kb = 0; kb < 4; kb++) {
            const int pos = ((kb * 4 + t) ^ g) << 4;
            uint4 aq[4][2];
#pragma unroll
            for (int mt = 0; mt < 4; mt++)
#pragma unroll
                for (int hf = 0; hf < 2; hf++)
                    aq[mt][hf] = *(const uint4*)(Ab + stOff +
                                 (mt * 16 + hf * 8) * 256 + pos);
            uint4 wq[4];
#pragma unroll
            for (int nt = 0; nt < 4; nt++)
                wq[nt] = *(const uint4*)(Bb + stOff + nt * 8 * 256 + pos);

#pragma unroll
            for (int nt = 0; nt < 4; nt++)
#pragma unroll
                for (int mt = 0; mt < 4; mt++)
                    mma_bf16(acc[mt][nt], aq[mt][0].x, aq[mt][1].x,
                             aq[mt][0].y, aq[mt][1].y, wq[nt].x, wq[nt].y);
#pragma unroll
            for (int nt = 0; nt < 4; nt++)
#pragma unroll
                for (int mt = 0; mt < 4; mt++)
                    mma_bf16(acc[mt][nt], aq[mt][0].x, aq[mt][1].x,
                             aq[mt][0].y, aq[mt][1].y, wq[nt].z, wq[nt].w);
#pragma unroll
            for (int nt = 0; nt < 4; nt++)
#pragma unroll
                for (int mt = 0; mt < 4; mt++)
                    mma_bf16(acc[mt][nt], aq[mt][0].z, aq[mt][1].z,
                             aq[mt][0].w, aq[mt][1].w, wq[nt].x, wq[nt].y);
        }
        __syncthreads();
    }

    float2 bv[4];
#pragma unroll
    for (int nt = 0; nt < 4; nt++)
        bv[nt] = *(const float2*)(b_ih + nbase + nslot * 32 + nt * 8 + 2 * t);

#pragma unroll
    for (int mt = 0; mt < 4; mt++) {
        const size_t r0 = (size_t)(mbase + mslot * 64 + mt * 16 + g) * H_;
        const size_t r1 = r0 + 8 * H_;
#pragma unroll
        for (int nt = 0; nt < 4; nt++) {
            const int col = nbase + nslot * 32 + nt * 8 + 2 * t;
            *(float2*)(g_embp + r0 + col) =
                make_float2(acc[mt][nt][0] + bv[nt].x, acc[mt][nt][1] + bv[nt].y);
            *(float2*)(g_embp + r1 + col) =
                make_float2(acc[mt][nt][2] + bv[nt].x, acc[mt][nt][3] + bv[nt].y);
        }
    }
}

// ---------------------------------------------------------------------------
// Classifier GEMM (scalar, tiny)
// ---------------------------------------------------------------------------
__global__ __launch_bounds__(256) void gemm_clf(
    const float* __restrict__ A, const float* __restrict__ W,
    const float* __restrict__ bias, float* __restrict__ C, int N, int K)
{
    __shared__ float As[16][36];
    __shared__ float Bs[16][68];

    const int tid = threadIdx.x;
    const int rowBase = blockIdx.y * 32;
    const int colBase = blockIdx.x * 64;
    const int tr = tid >> 5;
    const int tc = tid & 31;

    float acc[4][2];
#pragma unroll
    for (int i = 0; i < 4; i++) { acc[i][0] = 0.f; acc[i][1] = 0.f; }

    for (int k0 = 0; k0 < K; k0 += 16) {
        if (tid < 128) {
            int m = tid >> 2, q = tid & 3;
            float4 a = *(const float4*)(A + (size_t)(rowBase + m) * K + k0 + q * 4);
            As[q * 4 + 0][m] = a.x; As[q * 4 + 1][m] = a.y;
            As[q * 4 + 2][m] = a.z; As[q * 4 + 3][m] = a.w;
        }
        {
            int n = tid >> 2, q = tid & 3;
            float4 w = *(const float4*)(W + (size_t)(colBase + n) * K + k0 + q * 4);
            Bs[q * 4 + 0][n] = w.x; Bs[q * 4 + 1][n] = w.y;
            Bs[q * 4 + 2][n] = w.z; Bs[q * 4 + 3][n] = w.w;
        }
        __syncthreads();

#pragma unroll
        for (int kk = 0; kk < 16; kk++) {
            float ra[4], rb[2];
#pragma unroll
            for (int i = 0; i < 4; i++) ra[i] = As[kk][tr * 4 + i];
            rb[0] = Bs[kk][tc * 2 + 0];
            rb[1] = Bs[kk][tc * 2 + 1];
#pragma unroll
            for (int i = 0; i < 4; i++) {
                acc[i][0] += ra[i] * rb[0];
                acc[i][1] += ra[i] * rb[1];
            }
        }
        __syncthreads();
    }

#pragma unroll
    for (int i = 0; i < 4; i++) {
        int row = rowBase + tr * 4 + i;
#pragma unroll
        for (int j = 0; j < 2; j++) {
            int col = colBase + tc * 2 + j;
            C[(size_t)row * N + col] = acc[i][j] + bias[col];
        }
    }
}

// ---------------------------------------------------------------------------
// Init kernels
// ---------------------------------------------------------------------------
__global__ void zero_init_kernel() {
    int i = blockIdx.x * blockDim.x + threadIdx.x;
    if (i < B_ * 1024) g_hz[0][i] = 0u;
    if (i == 0) g_bar = 0;
}

// fp32 [rows, 1024] -> Z-layout bf16 hi/lo
__global__ void split_kernel(const float* __restrict__ W, uint32_t* __restrict__ dst,
                             int rows)
{
    int idx = blockIdx.x * blockDim.x + threadIdx.x;
    if (idx >= rows * 512) return;
    int n = idx >> 9, p = idx & 511;
    int col = 2 * p;
    float w0 = W[(size_t)n * 1024 + col];
    float w1 = W[(size_t)n * 1024 + col + 1];
    uint32_t hiU = pack_bf16(w0, w1);
    float r0 = w0 - __uint_as_float(hiU << 16);
    float r1 = w1 - __uint_as_float(hiU & 0xFFFF0000u);
    uint32_t loU = pack_bf16(r0, r1);
    int kb = col >> 4;
    int pp = (col >> 1) & 7;
    uint32_t* d = dst + ((size_t)n << 10) + kb * 16 + (pp & 3) * 4;
    d[pp >> 2] = hiU;
    d[(pp >> 2) + 2] = loU;
}

// ---------------------------------------------------------------------------
extern "C" void kernel_launch(void* const* d_in, const int* in_sizes, int n_in,
                              void* d_out, int out_size)
{
    const int*   x     = (const int*)d_in[0];
    const float* emb   = (const float*)d_in[1];
    const float* W_ih  = (const float*)d_in[2];
    const float* b_ih  = (const float*)d_in[3];
    const float* W_hh  = (const float*)d_in[4];
    const float* b_hh  = (const float*)d_in[5];
    const float* W_clf = (const float*)d_in[6];
    const float* b_clf = (const float*)d_in[7];
    float*       out   = (float*)d_out;

    float* hf = nullptr;
    uint32_t *wz = nullptr, *wihz = nullptr, *embz = nullptr;
    cudaGetSymbolAddress((void**)&hf, g_hf);
    cudaGetSymbolAddress((void**)&wz, g_wz);
    cudaGetSymbolAddress((void**)&wihz, g_wihz);
    cudaGetSymbolAddress((void**)&embz, g_embz);

    static bool attrSet = false;
    if (!attrSet) {
        cudaFuncSetAttribute(rnn_scan_kernel,
                             cudaFuncAttributeMaxDynamicSharedMemorySize, SCAN_SMEM);
        cudaFuncSetAttribute(embtab_mma_kernel,
                             cudaFuncAttributeMaxDynamicSharedMemorySize, PJ_SMEM);
        attrSet = true;
    }

    // init + conversions
    zero_init_kernel<<<(B_ * 1024 + 255) / 256, 256>>>();
    split_kernel<<<(H_ * 512 + 255) / 256, 256>>>(W_hh, wz, H_);
    split_kernel<<<(H_ * 512 + 255) / 256, 256>>>(W_ih, wihz, H_);
    split_kernel<<<(V_ * 512 + 255) / 256, 256>>>(emb, embz, V_);

    // dense table projection: emb_proj = emb @ W_ih^T + b_ih  (V x H)
    embtab_mma_kernel<<<dim3(H_ / 128, V_ / 128), 256, PJ_SMEM>>>(b_ih);

    // full scan in one persistent kernel (512 threads/CTA); xp read from table
    rnn_scan_kernel<<<NCTA, 512, SCAN_SMEM>>>(x, b_hh);

    // classifier
    gemm_clf<<<dim3(O_ / 64, B_ / 32), 256>>>(hf, W_clf, b_clf, out, O_, H_);
}

// round 15
// speedup vs baseline: 2.3079x; 1.0084x over previous
#include <cuda_runtime.h>
#include <cuda_bf16.h>
#include <math.h>
#include <stdint.h>

#define B_ 256
#define S_ 512
#define V_ 32000
#define E_ 1024
#define H_ 1024
#define O_ 512
#define NCTA 128

// ---------------------------------------------------------------------------
// Device scratch
// Z-quad layout (bf16 hi/lo) per row of K=1024:
//   1024 u32 per row; for k16 block KB, t in 0..3: uint4 at u32 (KB*16 + t*4) =
//   [hiPair(2t,2t+1), hiPair(2t+8,2t+9), loPair(2t,2t+1), loPair(2t+8,2t+9)]
// ---------------------------------------------------------------------------
__device__ float    g_embp[(size_t)V_ * H_];    // projected embedding table (128 MB)
__device__ float    g_hf[B_ * H_];              // final hidden state (fp32 plain)
__device__ uint32_t g_wz[H_ * 1024];            // W_hh  Z-layout (4 MB)
__device__ uint32_t g_wihz[H_ * 1024];          // W_ih  Z-layout (4 MB)
__device__ uint32_t g_embz[(size_t)V_ * 1024];  // emb Z-layout (128 MB)
__device__ uint32_t g_hz[2][B_ * 1024];         // h Z-layout, double buffered
__device__ int      g_barc[4 * 64];             // per-mgroup counters, 256B apart

// conflict-free row mask: adjacent rows differ by 4 in the low-3 slot space
#define MROW(r) ((((r) & 1) << 2) | (((r) >> 1) & 3))

// ---------------------------------------------------------------------------
// Helpers
// ---------------------------------------------------------------------------
__device__ __forceinline__ uint32_t smem_u32(const void* p) {
    uint32_t a;
    asm("{ .reg .u64 t; cvta.to.shared.u64 t, %1; cvt.u32.u64 %0, t; }" : "=r"(a) : "l"(p));
    return a;
}
__device__ __forceinline__ uint32_t pack_bf16(float lo, float hi) {
    uint32_t u; asm("cvt.rn.bf16x2.f32 %0, %1, %2;" : "=r"(u) : "f"(hi), "f"(lo));
    return u;
}

#define CP_ASYNC16(dst, src) \
    asm volatile("cp.async.cg.shared.global [%0], [%1], 16;" :: "r"(dst), "l"(src))
#define CP_COMMIT() asm volatile("cp.async.commit_group;" ::: "memory")
#define CP_WAIT0()  asm volatile("cp.async.wait_group 0;" ::: "memory")
#define CP_WAIT1()  asm volatile("cp.async.wait_group 1;" ::: "memory")
#define CP_WAIT2()  asm volatile("cp.async.wait_group 2;" ::: "memory")

// D += A*B  (m16n8k16 bf16, row.col, fp32 accum)
__device__ __forceinline__ void mma_bf16(float* c,
    uint32_t a0, uint32_t a1, uint32_t a2, uint32_t a3, uint32_t b0, uint32_t b1)
{
    asm volatile(
        "mma.sync.aligned.m16n8k16.row.col.f32.bf16.bf16.f32 "
        "{%0,%1,%2,%3}, {%4,%5,%6,%7}, {%8,%9}, {%0,%1,%2,%3};"
        : "+f"(c[0]), "+f"(c[1]), "+f"(c[2]), "+f"(c[3])
        : "r"(a0), "r"(a1), "r"(a2), "r"(a3), "r"(b0), "r"(b1));
}

// ---------------------------------------------------------------------------
// Persistent scan kernel (R14 structure; barrier scoped to 32-CTA mgroups).
// 128 CTAs x 512 thr (16 warps). CTA tile M=64 x N=32.
// Warp wid = kgrp*2 + mslot. One __syncthreads per K iteration.
// ---------------------------------------------------------------------------
#define W_BYTES   131072
#define STG_BYTES 32768
#define SCAN_SMEM (W_BYTES + 3 * STG_BYTES)   // 229376
#define NIT 8

__global__ __launch_bounds__(512, 1) void rnn_scan_kernel(
    const int* __restrict__ x, const float* __restrict__ b_hh)
{
    extern __shared__ char sm[];
    char* smW = sm;
    char* smA = sm + W_BYTES;
    const uint32_t smWu = smem_u32(smW);
    const uint32_t smAu = smem_u32(smA);

    const int tid = threadIdx.x;
    const int wid = tid >> 5, lane = tid & 31;
    const int g = lane >> 2, t = lane & 3;
    const int mslot = wid & 1, kgrp = wid >> 1;

    const int cta = blockIdx.x;
    const int nblk = cta & 31, mblk = cta >> 5;
    const int nbase = nblk * 32, mbase = mblk * 64;

    int* barp = g_barc + mblk * 64;          // this mgroup's counter (256B apart)

    // ---- resident W slice load (once): 32 rows x 256 chunks ----
    for (int j = 0; j < 16; j++) {
        int idx = tid + j * 512;
        int n = idx >> 8, c = idx & 255;
        int mr = MROW(n);
        uint32_t dst = smWu + n * 4096 + (((c & ~7) | ((c ^ mr) & 7)) << 4);
        CP_ASYNC16(dst, g_wz + (((size_t)(nbase + n)) << 10) + (c << 2));
    }
    CP_COMMIT(); CP_WAIT0();
    __syncthreads();

    // ---- thread-constant MMA operand offsets ----
    const int gm = MROW(g);
    const int achunk = ((kgrp & 6) << 2) + (((((kgrp & 1) << 2) + t)) ^ gm);
    const uint32_t abase = (uint32_t)achunk << 4;
    uint32_t aoff[4];
#pragma unroll
    for (int mt = 0; mt < 2; mt++)
#pragma unroll
        for (int hf = 0; hf < 2; hf++)
            aoff[mt * 2 + hf] = (mslot * 32 + mt * 16 + hf * 8 + g) * 512 + abase;
    uint32_t woff[4];
#pragma unroll
    for (int nt = 0; nt < 4; nt++)
        woff[nt] = (nt * 8 + g) * 4096 + abase;

    // ---- epilogue thread-constant mapping ----
    const int erow = tid >> 3;
    const int pc = tid & 7;
    const int mslot_r = erow >> 5, mt_r = (erow >> 4) & 1;
    const int hf_r = (erow >> 3) & 1, g_r = erow & 7;
    const size_t growbase = ((size_t)(mbase + erow)) << 10;
    const int* xrow = x + (mbase + erow) * S_;   // tokens for this output row

    int roff[2], colv[2], zoff[2];
    float2 bvv[2];
#pragma unroll
    for (int i = 0; i < 2; i++) {
        int p = pc + i * 8;
        int nt_r = p >> 2, t_r = p & 3;
        int lane_r = g_r * 4 + t_r;
        int q_r = mt_r * 4 + nt_r;
        roff[i] = lane_r * 32 + ((q_r ^ (lane_r & 7)) << 2) + 2 * hf_r;
        int col = nbase + 2 * p;
        colv[i] = col;
        bvv[i] = *(const float2*)(b_hh + col);
        int kb = col >> 4;
        int pp = (col >> 1) & 7;
        zoff[i] = kb * 16 + (pp & 3) * 4 + (pp >> 2);
    }

    float* dumpf = (float*)smA;

    int tok = xrow[0];                           // first-step token preloaded

#pragma unroll 1
    for (int s = 0; s < S_; s++) {
        const uint32_t* hzin = g_hz[s & 1];
        uint32_t* hzout = g_hz[(s + 1) & 1];

        // ---- prefetch xp = emb_proj[token] (latency hidden under MMA loop) ----
        const float* eprow = g_embp + ((size_t)tok << 10);
        float2 xvv[2];
#pragma unroll
        for (int i = 0; i < 2; i++)
            xvv[i] = *(const float2*)(eprow + colv[i]);

        // ---- prefill stages 0,1 (k-slabs 0,1) ----
#pragma unroll
        for (int st = 0; st < 2; st++) {
#pragma unroll
            for (int j = 0; j < 4; j++) {
                int idx = tid + j * 512;
                int row = idx >> 5, cc = idx & 31;
                int mr = MROW(row);
                uint32_t dst = smAu + st * STG_BYTES + row * 512 +
                               (((cc & ~7) | ((cc ^ mr) & 7)) << 4);
                CP_ASYNC16(dst, hzin + (((size_t)(mbase + row)) << 10) +
                                ((st * 32 + cc) << 2));
            }
            CP_COMMIT();
        }

        float acc[8][4];
#pragma unroll
        for (int q = 0; q < 8; q++)
#pragma unroll
            for (int i = 0; i < 4; i++) acc[q][i] = 0.f;

        // ---- K loop: one sync per iteration ----
#pragma unroll
        for (int it = 0; it < NIT; it++) {
            if (it < NIT - 1) { CP_WAIT1(); } else { CP_WAIT0(); }
            __syncthreads();

            if (it + 2 < NIT) {
                int st = (it + 2) % 3;
#pragma unroll
                for (int j = 0; j < 4; j++) {
                    int idx = tid + j * 512;
                    int row = idx >> 5, cc = idx & 31;
                    int mr = MROW(row);
                    uint32_t dst = smAu + st * STG_BYTES + row * 512 +
                                   (((cc & ~7) | ((cc ^ mr) & 7)) << 4);
                    CP_ASYNC16(dst, hzin + (((size_t)(mbase + row)) << 10) +
                                    (((it + 2) * 32 + cc) << 2));
                }
                CP_COMMIT();
            }

            const char* stg = smA + (it % 3) * STG_BYTES;
            uint4 aq[2][2];
#pragma unroll
            for (int mt = 0; mt < 2; mt++)
#pragma unroll
                for (int hf = 0; hf < 2; hf++)
                    aq[mt][hf] = *(const uint4*)(stg + aoff[mt * 2 + hf]);
            uint4 wq[4];
#pragma unroll
            for (int nt = 0; nt < 4; nt++)
                wq[nt] = *(const uint4*)(smW + woff[nt] + it * 512);

#pragma unroll
            for (int nt = 0; nt < 4; nt++)
#pragma unroll
                for (int mt = 0; mt < 2; mt++)
                    mma_bf16(acc[mt * 4 + nt], aq[mt][0].x, aq[mt][1].x,
                             aq[mt][0].y, aq[mt][1].y, wq[nt].x, wq[nt].y);
#pragma unroll
            for (int nt = 0; nt < 4; nt++)
#pragma unroll
                for (int mt = 0; mt < 2; mt++)
                    mma_bf16(acc[mt * 4 + nt], aq[mt][0].x, aq[mt][1].x,
                             aq[mt][0].y, aq[mt][1].y, wq[nt].z, wq[nt].w);
#pragma unroll
            for (int nt = 0; nt < 4; nt++)
#pragma unroll
                for (int mt = 0; mt < 2; mt++)
                    mma_bf16(acc[mt * 4 + nt], aq[mt][0].z, aq[mt][1].z,
                             aq[mt][0].w, aq[mt][1].w, wq[nt].x, wq[nt].y);
        }

        // next-step token prefetch (independent LDG, hidden under epilogue)
        if (s + 1 < S_) tok = xrow[s + 1];

        __syncthreads();   // stage smem free -> reuse as reduction buffer

        // ---- dump partials: 16 warps x 4 KB = 64 KB ----
        {
            float* wr = dumpf + wid * 1024 + lane * 32;
#pragma unroll
            for (int q = 0; q < 8; q++)
                *(float4*)(wr + ((q ^ (lane & 7)) << 2)) =
                    make_float4(acc[q][0], acc[q][1], acc[q][2], acc[q][3]);
        }
        __syncthreads();

        // ---- epilogue: 8-way K reduce + tanh + Z-pack store ----
#pragma unroll
        for (int i = 0; i < 2; i++) {
            float s0 = 0.f, s1 = 0.f;
#pragma unroll
            for (int k = 0; k < 8; k++) {
                const float* rr = dumpf + (k * 2 + mslot_r) * 1024 + roff[i];
                s0 += rr[0]; s1 += rr[1];
            }
            float v0 = tanhf(s0 + xvv[i].x + bvv[i].x);
            float v1 = tanhf(s1 + xvv[i].y + bvv[i].y);

            uint32_t hiU = pack_bf16(v0, v1);
            float r0 = v0 - __uint_as_float(hiU << 16);
            float r1 = v1 - __uint_as_float(hiU & 0xFFFF0000u);
            uint32_t loU = pack_bf16(r0, r1);

            uint32_t* dst = hzout + growbase + zoff[i];
            dst[0] = hiU;
            dst[2] = loU;

            if (s == S_ - 1)
                *(float2*)(g_hf + growbase + colv[i]) = make_float2(v0, v1);
        }

        __syncthreads();

        // ---- per-mgroup barrier (32 arrivals, own L2 line) ----
        if (tid == 0) {
            __threadfence();
            atomicAdd(barp, 1);
            int target = 32 * (s + 1);
            while (*(volatile int*)barp < target) {}
            __threadfence();
        }
        __syncthreads();
    }
}

// ---------------------------------------------------------------------------
// Dense embedding-table projection: emb_proj = emb @ W_ih^T + b_ih
// M over V=32000 rows (250 tiles of 128), N=1024 (8 tiles of 128).
// ---------------------------------------------------------------------------
#define PJ_STG 65536
#define PJ_SMEM (3 * PJ_STG)
#define PJ_NIT 16

__global__ __launch_bounds__(256, 1) void embtab_mma_kernel(const float* __restrict__ b_ih)
{
    extern __shared__ char sm[];
    const uint32_t smu = smem_u32(sm);

    const int tid = threadIdx.x;
    const int wid = tid >> 5, lane = tid & 31;
    const int g = lane >> 2, t = lane & 3;
    const int mslot = wid & 1, nslot = wid >> 1;

    const int nbase = blockIdx.x * 128;
    const int mbase = blockIdx.y * 128;

    const int lrow = tid >> 4;
    const int lcc  = tid & 15;
    const uint32_t lpos = (uint32_t)((lcc ^ (lrow & 7)) << 4);
    const uint32_t* asrc = g_embz + (size_t)(mbase + lrow) * 1024 + lcc * 4;
    const uint32_t* bsrc = g_wihz + (size_t)(nbase + lrow) * 1024 + lcc * 4;

    float acc[4][4][4];
#pragma unroll
    for (int mt = 0; mt < 4; mt++)
#pragma unroll
        for (int nt = 0; nt < 4; nt++)
#pragma unroll
            for (int i = 0; i < 4; i++) acc[mt][nt][i] = 0.f;

#pragma unroll
    for (int st = 0; st < 2; st++) {
        uint32_t sb = smu + st * PJ_STG;
        int k0 = st * 64;
#pragma unroll
        for (int j = 0; j < 8; j++) {
            uint32_t d = (lrow + 16 * j) * 256 + lpos;
            CP_ASYNC16(sb + d, asrc + (size_t)j * 16 * 1024 + k0);
            CP_ASYNC16(sb + 32768 + d, bsrc + (size_t)j * 16 * 1024 + k0);
        }
        CP_COMMIT();
    }

    const char* Ab = sm + (mslot * 64 + g) * 256;
    const char* Bb = sm + 32768 + (nslot * 32 + g) * 256;

    for (int it = 0; it < PJ_NIT; it++) {
        if (it + 2 < PJ_NIT) {
            uint32_t sb = smu + ((it + 2) % 3) * PJ_STG;
            int k0 = (it + 2) * 64;
#pragma unroll
            for (int j = 0; j < 8; j++) {
                uint32_t d = (lrow + 16 * j) * 256 + lpos;
                CP_ASYNC16(sb + d, asrc + (size_t)j * 16 * 1024 + k0);
                CP_ASYNC16(sb + 32768 + d, bsrc + (size_t)j * 16 * 1024 + k0);
            }
            CP_COMMIT();
            CP_WAIT2();
        } else if (it + 1 < PJ_NIT) {
            CP_WAIT1();
        } else {
            CP_WAIT0();
        }
        __syncthreads();

        const int stOff = (it % 3) * PJ_STG;
#pragma unroll
        for (int kb = 0; kb < 4; kb++) {
            const int pos = ((kb * 4 + t) ^ g) << 4;
            uint4 aq[4][2];
#pragma unroll
            for (int mt = 0; mt < 4; mt++)
#pragma unroll
                for (int hf = 0; hf < 2; hf++)
                    aq[mt][hf] = *(const uint4*)(Ab + stOff +
                                 (mt * 16 + hf * 8) * 256 + pos);
            uint4 wq[4];
#pragma unroll
            for (int nt = 0; nt < 4; nt++)
                wq[nt] = *(const uint4*)(Bb + stOff + nt * 8 * 256 + pos);

#pragma unroll
            for (int nt = 0; nt < 4; nt++)
#pragma unroll
                for (int mt = 0; mt < 4; mt++)
                    mma_bf16(acc[mt][nt], aq[mt][0].x, aq[mt][1].x,
                             aq[mt][0].y, aq[mt][1].y, wq[nt].x, wq[nt].y);
#pragma unroll
            for (int nt = 0; nt < 4; nt++)
#pragma unroll
                for (int mt = 0; mt < 4; mt++)
                    mma_bf16(acc[mt][nt], aq[mt][0].x, aq[mt][1].x,
                             aq[mt][0].y, aq[mt][1].y, wq[nt].z, wq[nt].w);
#pragma unroll
            for (int nt = 0; nt < 4; nt++)
#pragma unroll
                for (int mt = 0; mt < 4; mt++)
                    mma_bf16(acc[mt][nt], aq[mt][0].z, aq[mt][1].z,
                             aq[mt][0].w, aq[mt][1].w, wq[nt].x, wq[nt].y);
        }
        __syncthreads();
    }

    float2 bv[4];
#pragma unroll
    for (int nt = 0; nt < 4; nt++)
        bv[nt] = *(const float2*)(b_ih + nbase + nslot * 32 + nt * 8 + 2 * t);

#pragma unroll
    for (int mt = 0; mt < 4; mt++) {
        const size_t r0 = (size_t)(mbase + mslot * 64 + mt * 16 + g) * H_;
        const size_t r1 = r0 + 8 * H_;
#pragma unroll
        for (int nt = 0; nt < 4; nt++) {
            const int col = nbase + nslot * 32 + nt * 8 + 2 * t;
            *(float2*)(g_embp + r0 + col) =
                make_float2(acc[mt][nt][0] + bv[nt].x, acc[mt][nt][1] + bv[nt].y);
            *(float2*)(g_embp + r1 + col) =
                make_float2(acc[mt][nt][2] + bv[nt].x, acc[mt][nt][3] + bv[nt].y);
        }
    }
}

// ---------------------------------------------------------------------------
// Classifier GEMM (scalar, tiny)
// ---------------------------------------------------------------------------
__global__ __launch_bounds__(256) void gemm_clf(
    const float* __restrict__ A, const float* __restrict__ W,
    const float* __restrict__ bias, float* __restrict__ C, int N, int K)
{
    __shared__ float As[16][36];
    __shared__ float Bs[16][68];

    const int tid = threadIdx.x;
    const int rowBase = blockIdx.y * 32;
    const int colBase = blockIdx.x * 64;
    const int tr = tid >> 5;
    const int tc = tid & 31;

    float acc[4][2];
#pragma unroll
    for (int i = 0; i < 4; i++) { acc[i][0] = 0.f; acc[i][1] = 0.f; }

    for (int k0 = 0; k0 < K; k0 += 16) {
        if (tid < 128) {
            int m = tid >> 2, q = tid & 3;
            float4 a = *(const float4*)(A + (size_t)(rowBase + m) * K + k0 + q * 4);
            As[q * 4 + 0][m] = a.x; As[q * 4 + 1][m] = a.y;
            As[q * 4 + 2][m] = a.z; As[q * 4 + 3][m] = a.w;
        }
        {
            int n = tid >> 2, q = tid & 3;
            float4 w = *(const float4*)(W + (size_t)(colBase + n) * K + k0 + q * 4);
            Bs[q * 4 + 0][n] = w.x; Bs[q * 4 + 1][n] = w.y;
            Bs[q * 4 + 2][n] = w.z; Bs[q * 4 + 3][n] = w.w;
        }
        __syncthreads();

#pragma unroll
        for (int kk = 0; kk < 16; kk++) {
            float ra[4], rb[2];
#pragma unroll
            for (int i = 0; i < 4; i++) ra[i] = As[kk][tr * 4 + i];
            rb[0] = Bs[kk][tc * 2 + 0];
            rb[1] = Bs[kk][tc * 2 + 1];
#pragma unroll
            for (int i = 0; i < 4; i++) {
                acc[i][0] += ra[i] * rb[0];
                acc[i][1] += ra[i] * rb[1];
            }
        }
        __syncthreads();
    }

#pragma unroll
    for (int i = 0; i < 4; i++) {
        int row = rowBase + tr * 4 + i;
#pragma unroll
        for (int j = 0; j < 2; j++) {
            int col = colBase + tc * 2 + j;
            C[(size_t)row * N + col] = acc[i][j] + bias[col];
        }
    }
}

// ---------------------------------------------------------------------------
// Init kernels
// ---------------------------------------------------------------------------
__global__ void zero_init_kernel() {
    int i = blockIdx.x * blockDim.x + threadIdx.x;
    if (i < B_ * 1024) g_hz[0][i] = 0u;
    if (i < 4 * 64) g_barc[i] = 0;
}

// fp32 [rows, 1024] -> Z-layout bf16 hi/lo
__global__ void split_kernel(const float* __restrict__ W, uint32_t* __restrict__ dst,
                             int rows)
{
    int idx = blockIdx.x * blockDim.x + threadIdx.x;
    if (idx >= rows * 512) return;
    int n = idx >> 9, p = idx & 511;
    int col = 2 * p;
    float w0 = W[(size_t)n * 1024 + col];
    float w1 = W[(size_t)n * 1024 + col + 1];
    uint32_t hiU = pack_bf16(w0, w1);
    float r0 = w0 - __uint_as_float(hiU << 16);
    float r1 = w1 - __uint_as_float(hiU & 0xFFFF0000u);
    uint32_t loU = pack_bf16(r0, r1);
    int kb = col >> 4;
    int pp = (col >> 1) & 7;
    uint32_t* d = dst + ((size_t)n << 10) + kb * 16 + (pp & 3) * 4;
    d[pp >> 2] = hiU;
    d[(pp >> 2) + 2] = loU;
}

// ---------------------------------------------------------------------------
extern "C" void kernel_launch(void* const* d_in, const int* in_sizes, int n_in,
                              void* d_out, int out_size)
{
    const int*   x     = (const int*)d_in[0];
    const float* emb   = (const float*)d_in[1];
    const float* W_ih  = (const float*)d_in[2];
    const float* b_ih  = (const float*)d_in[3];
    const float* W_hh  = (const float*)d_in[4];
    const float* b_hh  = (const float*)d_in[5];
    const float* W_clf = (const float*)d_in[6];
    const float* b_clf = (const float*)d_in[7];
    float*       out   = (float*)d_out;

    float* hf = nullptr;
    uint32_t *wz = nullptr, *wihz = nullptr, *embz = nullptr;
    cudaGetSymbolAddress((void**)&hf, g_hf);
    cudaGetSymbolAddress((void**)&wz, g_wz);
    cudaGetSymbolAddress((void**)&wihz, g_wihz);
    cudaGetSymbolAddress((void**)&embz, g_embz);

    static bool attrSet = false;
    if (!attrSet) {
        cudaFuncSetAttribute(rnn_scan_kernel,
                             cudaFuncAttributeMaxDynamicSharedMemorySize, SCAN_SMEM);
        cudaFuncSetAttribute(embtab_mma_kernel,
                             cudaFuncAttributeMaxDynamicSharedMemorySize, PJ_SMEM);
        attrSet = true;
    }

    // init + conversions
    zero_init_kernel<<<(B_ * 1024 + 255) / 256, 256>>>();
    split_kernel<<<(H_ * 512 + 255) / 256, 256>>>(W_hh, wz, H_);
    split_kernel<<<(H_ * 512 + 255) / 256, 256>>>(W_ih, wihz, H_);
    split_kernel<<<(V_ * 512 + 255) / 256, 256>>>(emb, embz, V_);

    // dense table projection: emb_proj = emb @ W_ih^T + b_ih  (V x H)
    embtab_mma_kernel<<<dim3(H_ / 128, V_ / 128), 256, PJ_SMEM>>>(b_ih);

    // full scan in one persistent kernel (512 threads/CTA); xp read from table
    rnn_scan_kernel<<<NCTA, 512, SCAN_SMEM>>>(x, b_hh);

    // classifier
    gemm_clf<<<dim3(O_ / 64, B_ / 32), 256>>>(hf, W_clf, b_clf, out, O_, H_);
}